// round 8
// baseline (speedup 1.0000x reference)
#include <cuda_runtime.h>
#include <cstdint>

// Reverse (suffix) cumulative sum along dim=1.
// x: (2048, 32768) fp32. out[b, j] = sum_{k >= j} x[b, k].
//
// R8: R5 compute path + TMA bulk STORE.
//  - One CTA per row, 1024 threads, coalesced interleaved register layout
//    (thread holds tile[i*32 + lane], i=0..7 -> full-width L1 wavefronts).
//  - 3-level suffix scan: intra-float4 -> per-slot warp shfl -> single-
//    barrier block scan of 32 warp totals.
//  - NEW: results are written to a 128 KB smem buffer (STS.128, conflict
//    free) and flushed with cp.async.bulk smem->global in 4 x 32 KB
//    contiguous chunks. Maximal DRAM write bursts, zero STG pressure.

#define N_COLS   32768
#define THREADS  1024
#define SLOTS    8
#define ROW_BYTES (N_COLS * 4)          // 131072
#define CHUNK    32768                  // bulk-store chunk bytes
#define NCHUNK   (ROW_BYTES / CHUNK)    // 4

__device__ __forceinline__ uint32_t smem_u32(const void* p) {
    uint32_t a;
    asm("{ .reg .u64 t; cvta.to.shared.u64 t, %1; cvt.u32.u64 %0, t; }"
        : "=r"(a) : "l"(p));
    return a;
}

__global__ __launch_bounds__(THREADS, 1)
void revcumsum_tma_kernel(const float* __restrict__ x, float* __restrict__ out) {
    extern __shared__ float sbuf[];       // 32768 floats = 128 KB
    __shared__ float warp_tot[32];

    const long long base = (long long)blockIdx.x * N_COLS;
    const int t    = threadIdx.x;
    const int lane = t & 31;
    const int wid  = t >> 5;

    const float4* __restrict__ xin =
        reinterpret_cast<const float4*>(x + base) + wid * 256 + lane;

    // ---- coalesced load: slot i at float4 index i*32 + lane ----
    float4 r[SLOTS];
    #pragma unroll
    for (int i = 0; i < SLOTS; i++) r[i] = xin[i * 32];

    // ---- suffix scan inside each float4 ----
    float s[SLOTS];
    #pragma unroll
    for (int i = 0; i < SLOTS; i++) {
        r[i].z += r[i].w;
        r[i].y += r[i].z;
        r[i].x += r[i].y;
        s[i] = r[i].x;
    }

    // ---- per-slot warp suffix scan over lanes ----
    float excl[SLOTS], T[SLOTS];
    #pragma unroll
    for (int i = 0; i < SLOTS; i++) {
        float incl = s[i];
        #pragma unroll
        for (int d = 1; d < 32; d <<= 1) {
            float tmp = __shfl_down_sync(0xFFFFFFFFu, incl, d);
            if (lane + d < 32) incl += tmp;
        }
        excl[i] = incl - s[i];
        T[i]    = __shfl_sync(0xFFFFFFFFu, incl, 0);
    }

    // ---- register suffix over slots ----
    float O[SLOTS];
    O[SLOTS - 1] = 0.0f;
    #pragma unroll
    for (int i = SLOTS - 2; i >= 0; i--) O[i] = O[i + 1] + T[i + 1];
    const float warp_total = O[0] + T[0];

    // ---- block suffix scan over 32 warp totals (single barrier) ----
    if (lane == 0) warp_tot[wid] = warp_total;
    __syncthreads();
    float w  = warp_tot[lane];
    float iw = w;
    #pragma unroll
    for (int d = 1; d < 32; d <<= 1) {
        float tmp = __shfl_down_sync(0xFFFFFFFFu, iw, d);
        if (lane + d < 32) iw += tmp;
    }
    const float woff = __shfl_sync(0xFFFFFFFFu, iw - w, wid);

    // ---- apply offsets, STS to smem buffer (same interleaved indices) ----
    float4* sb = reinterpret_cast<float4*>(sbuf) + wid * 256 + lane;
    #pragma unroll
    for (int i = 0; i < SLOTS; i++) {
        const float off = woff + O[i] + excl[i];
        float4 wv;
        wv.x = r[i].x + off;
        wv.y = r[i].y + off;
        wv.z = r[i].z + off;
        wv.w = r[i].w + off;
        sb[i * 32] = wv;
    }
    __syncthreads();

    // ---- TMA bulk store: 4 x 32 KB contiguous chunks ----
    if (t == 0) {
        asm volatile("fence.proxy.async.shared::cta;" ::: "memory");
        const uint32_t sbase = smem_u32(sbuf);
        float* gdst = out + base;
        #pragma unroll
        for (int c = 0; c < NCHUNK; c++) {
            asm volatile(
                "cp.async.bulk.global.shared::cta.bulk_group [%0], [%1], %2;"
                :: "l"(gdst + c * (CHUNK / 4)),
                   "r"(sbase + c * CHUNK),
                   "r"((unsigned)CHUNK) : "memory");
        }
        asm volatile("cp.async.bulk.commit_group;" ::: "memory");
        asm volatile("cp.async.bulk.wait_group 0;" ::: "memory");
    }
}

extern "C" void kernel_launch(void* const* d_in, const int* in_sizes, int n_in,
                              void* d_out, int out_size) {
    const float* x = (const float*)d_in[0];
    float* out = (float*)d_out;
    const int n    = in_sizes[0];       // B * N
    const int rows = n / N_COLS;        // 2048

    static bool attr_done = false;
    const int smem_bytes = ROW_BYTES;   // 128 KB dynamic
    if (!attr_done) {
        cudaFuncSetAttribute(revcumsum_tma_kernel,
                             cudaFuncAttributeMaxDynamicSharedMemorySize,
                             smem_bytes);
        attr_done = true;
    }

    revcumsum_tma_kernel<<<rows, THREADS, smem_bytes>>>(x, out);
}

// round 13
// speedup vs baseline: 1.0879x; 1.0879x over previous
#include <cuda_runtime.h>

// Reverse (suffix) cumulative sum along dim=1.
// x: (2048, 32768) fp32. out[b, j] = sum_{k >= j} x[b, k].
//
// R9 = R5 (best-known: coalesced interleaved layout, 3-level suffix scan,
//      single-barrier block scan, default cache policy)
//    + epilogue L2 prefetch of the SUCCESSOR CTA's row. Classic launch maps
//      bid and bid+148 to the same SM, so each CTA warms L2 for the CTA
//      that will run next on its SM -> next wave's loads hit L2 instead of
//      cold DRAM, shrinking the per-wave read-latency ramp.

#define N_COLS      32768
#define THREADS     1024
#define F4_PER_WARP 256   // 1024 floats per warp tile
#define SLOTS       8     // float4s per thread
#define NSM         148

__global__ __launch_bounds__(THREADS, 1)
void revcumsum_kernel(const float* __restrict__ x, float* __restrict__ out,
                      int rows) {
    const long long base = (long long)blockIdx.x * N_COLS;
    const int t    = threadIdx.x;
    const int lane = t & 31;
    const int wid  = t >> 5;

    const float4* __restrict__ xin =
        reinterpret_cast<const float4*>(x + base) + wid * F4_PER_WARP + lane;

    // ---- coalesced load: slot i at float4 index i*32 + lane ----
    float4 r[SLOTS];
    #pragma unroll
    for (int i = 0; i < SLOTS; i++) r[i] = xin[i * 32];

    // ---- suffix scan inside each float4; s[i] = group sum ----
    float s[SLOTS];
    #pragma unroll
    for (int i = 0; i < SLOTS; i++) {
        r[i].z += r[i].w;
        r[i].y += r[i].z;
        r[i].x += r[i].y;
        s[i] = r[i].x;
    }

    // ---- per-slot warp suffix scan over lanes ----
    float excl[SLOTS];   // sum of s[i] for lanes > my lane
    float T[SLOTS];      // warp-wide total of slot i
    #pragma unroll
    for (int i = 0; i < SLOTS; i++) {
        float incl = s[i];
        #pragma unroll
        for (int d = 1; d < 32; d <<= 1) {
            float tmp = __shfl_down_sync(0xFFFFFFFFu, incl, d);
            if (lane + d < 32) incl += tmp;
        }
        excl[i] = incl - s[i];
        T[i]    = __shfl_sync(0xFFFFFFFFu, incl, 0);
    }

    // ---- register suffix over slots: O[i] = sum of T[i'] for i' > i ----
    float O[SLOTS];
    O[SLOTS - 1] = 0.0f;
    #pragma unroll
    for (int i = SLOTS - 2; i >= 0; i--) O[i] = O[i + 1] + T[i + 1];
    const float warp_total = O[0] + T[0];

    // ---- block suffix scan over warp totals: ONE barrier, every warp
    //      redundantly scans the 32 totals and picks its own offset ----
    __shared__ float warp_tot[32];
    if (lane == 0) warp_tot[wid] = warp_total;
    __syncthreads();

    float w  = warp_tot[lane];
    float iw = w;
    #pragma unroll
    for (int d = 1; d < 32; d <<= 1) {
        float tmp = __shfl_down_sync(0xFFFFFFFFu, iw, d);
        if (lane + d < 32) iw += tmp;
    }
    const float woff = __shfl_sync(0xFFFFFFFFu, iw - w, wid);

    // ---- apply offsets, coalesced store (default policy) ----
    float4* __restrict__ o =
        reinterpret_cast<float4*>(out + base) + wid * F4_PER_WARP + lane;
    #pragma unroll
    for (int i = 0; i < SLOTS; i++) {
        const float off = woff + O[i] + excl[i];
        float4 wv;
        wv.x = r[i].x + off;
        wv.y = r[i].y + off;
        wv.z = r[i].z + off;
        wv.w = r[i].w + off;
        o[i * 32] = wv;
    }

    // ---- epilogue: warm L2 for the successor CTA on this SM ----
    // bid+NSM maps to the same SM (classic launch: LUT[bid % 148]).
    // Each 128B line holds 8 float4s; lanes with lane%8==0 cover the
    // warp tile's 32 lines exactly once.
    const int nbid = blockIdx.x + NSM;
    if (nbid < rows && (lane & 7) == 0) {
        const float4* nxt =
            reinterpret_cast<const float4*>(x + (long long)nbid * N_COLS) +
            wid * F4_PER_WARP + lane;
        #pragma unroll
        for (int i = 0; i < SLOTS; i++) {
            asm volatile("prefetch.global.L2 [%0];" :: "l"(&nxt[i * 32]));
        }
    }
}

extern "C" void kernel_launch(void* const* d_in, const int* in_sizes, int n_in,
                              void* d_out, int out_size) {
    const float* x = (const float*)d_in[0];
    float* out = (float*)d_out;
    const int n    = in_sizes[0];       // B * N
    const int rows = n / N_COLS;        // 2048
    revcumsum_kernel<<<rows, THREADS>>>(x, out, rows);
}

// round 14
// speedup vs baseline: 1.1219x; 1.0312x over previous
#include <cuda_runtime.h>

// Reverse (suffix) cumulative sum along dim=1.
// x: (2048, 32768) fp32. out[b, j] = sum_{k >= j} x[b, k].
//
// R14 = R5 structure with 256-bit vector memory ops (Blackwell LDG.E.256 /
// STG.E.256 via ld/st.global.v8.f32):
//  - One CTA per row, 1024 threads. Warp tile = 1024 floats.
//  - Thread holds 4 slots of 8 consecutive floats; slot i at float offset
//    warp_base + i*256 + lane*8 (lane stride 32 B -> each LDG.256 covers
//    8 contiguous 128B lines, fully coalesced).
//  - Suffix scan: 7 adds inside each float8 -> 4 warp shfl chains ->
//    register suffix over 4 slots -> single-barrier block scan of 32
//    warp totals (every warp redundantly scans, picks own offset).
//  - Half the memory instructions and half the warp-scan work of R5.

#define N_COLS   32768
#define THREADS  1024
#define SLOTS    4        // float8s per thread
#define VEC      8        // floats per vector op

__global__ __launch_bounds__(THREADS, 1)
void revcumsum_kernel(const float* __restrict__ x, float* __restrict__ out) {
    const long long base = (long long)blockIdx.x * N_COLS;
    const int t    = threadIdx.x;
    const int lane = t & 31;
    const int wid  = t >> 5;

    // warp tile = 1024 floats; slot i at warp_base + i*256 + lane*8
    const float* __restrict__ xin = x + base + wid * 1024 + lane * VEC;

    // ---- 256-bit coalesced loads ----
    float v[SLOTS][VEC];
    #pragma unroll
    for (int i = 0; i < SLOTS; i++) {
        asm volatile(
            "ld.global.v8.f32 {%0,%1,%2,%3,%4,%5,%6,%7}, [%8];"
            : "=f"(v[i][0]), "=f"(v[i][1]), "=f"(v[i][2]), "=f"(v[i][3]),
              "=f"(v[i][4]), "=f"(v[i][5]), "=f"(v[i][6]), "=f"(v[i][7])
            : "l"(xin + i * 256));
    }

    // ---- suffix scan inside each float8; s[i] = group sum ----
    float s[SLOTS];
    #pragma unroll
    for (int i = 0; i < SLOTS; i++) {
        #pragma unroll
        for (int j = VEC - 2; j >= 0; j--) v[i][j] += v[i][j + 1];
        s[i] = v[i][0];
    }

    // ---- per-slot warp suffix scan over lanes ----
    float excl[SLOTS];   // sum of s[i] for lanes > my lane
    float T[SLOTS];      // warp-wide total of slot i
    #pragma unroll
    for (int i = 0; i < SLOTS; i++) {
        float incl = s[i];
        #pragma unroll
        for (int d = 1; d < 32; d <<= 1) {
            float tmp = __shfl_down_sync(0xFFFFFFFFu, incl, d);
            if (lane + d < 32) incl += tmp;
        }
        excl[i] = incl - s[i];
        T[i]    = __shfl_sync(0xFFFFFFFFu, incl, 0);
    }

    // ---- register suffix over slots: O[i] = sum of T[i'] for i' > i ----
    float O[SLOTS];
    O[SLOTS - 1] = 0.0f;
    #pragma unroll
    for (int i = SLOTS - 2; i >= 0; i--) O[i] = O[i + 1] + T[i + 1];
    const float warp_total = O[0] + T[0];

    // ---- block suffix scan over 32 warp totals: single barrier ----
    __shared__ float warp_tot[32];
    if (lane == 0) warp_tot[wid] = warp_total;
    __syncthreads();

    float w  = warp_tot[lane];
    float iw = w;
    #pragma unroll
    for (int d = 1; d < 32; d <<= 1) {
        float tmp = __shfl_down_sync(0xFFFFFFFFu, iw, d);
        if (lane + d < 32) iw += tmp;
    }
    const float woff = __shfl_sync(0xFFFFFFFFu, iw - w, wid);

    // ---- apply offsets, 256-bit coalesced stores ----
    float* __restrict__ o = out + base + wid * 1024 + lane * VEC;
    #pragma unroll
    for (int i = 0; i < SLOTS; i++) {
        const float off = woff + O[i] + excl[i];
        float w0 = v[i][0] + off, w1 = v[i][1] + off;
        float w2 = v[i][2] + off, w3 = v[i][3] + off;
        float w4 = v[i][4] + off, w5 = v[i][5] + off;
        float w6 = v[i][6] + off, w7 = v[i][7] + off;
        asm volatile(
            "st.global.v8.f32 [%0], {%1,%2,%3,%4,%5,%6,%7,%8};"
            :: "l"(o + i * 256),
               "f"(w0), "f"(w1), "f"(w2), "f"(w3),
               "f"(w4), "f"(w5), "f"(w6), "f"(w7)
            : "memory");
    }
}

extern "C" void kernel_launch(void* const* d_in, const int* in_sizes, int n_in,
                              void* d_out, int out_size) {
    const float* x = (const float*)d_in[0];
    float* out = (float*)d_out;
    const int n    = in_sizes[0];       // B * N
    const int rows = n / N_COLS;        // 2048
    revcumsum_kernel<<<rows, THREADS>>>(x, out);
}